// round 16
// baseline (speedup 1.0000x reference)
#include <cuda_runtime.h>
#include <cuda_bf16.h>
#include <math.h>

#define SEQ     512
#define INDIM   512
#define HID     1024
#define GATES   4096   // 4*HID, gate order i,f,g,o
#define NCTA    128
#define NTHR    256

// ---------------- device scratch ----------------
__device__ float    g_gx[SEQ * GATES];     // 8 MB input-GEMM result (reused per pair)
__device__ float    g_h1[SEQ * HID];       // layer-1 h history (feeds gemm for layer 2)
__device__ float    g_h3[SEQ * HID];       // layer-3 h history (feeds final fc)
__device__ unsigned g_pubP[2][2 * HID];    // per-pair tagged pub: [0..1023]=h_a, [1024..2047]=h_b

__device__ __forceinline__ float sigm_fast(float x) { return 1.0f / (1.0f + __expf(-x)); }
__device__ __forceinline__ float tanh_fast(float x) { return 1.0f - 2.0f / (1.0f + __expf(2.0f * x)); }

__device__ __forceinline__ void st_rlx(unsigned* p, unsigned v) {
    asm volatile("st.relaxed.gpu.global.u32 [%0], %1;" :: "l"(p), "r"(v) : "memory");
}
__device__ __forceinline__ uint4 ld_rlx4(const uint4* p) {
    uint4 v;
    asm volatile("ld.relaxed.gpu.global.v4.u32 {%0,%1,%2,%3}, [%4];"
                 : "=r"(v.x), "=r"(v.y), "=r"(v.z), "=r"(v.w) : "l"(p));
    return v;
}
// unpack one bf16x2 weight reg and FMA against two h values
__device__ __forceinline__ void bfma(unsigned w, float hx, float hy, float& a0, float& a1) {
    a0 = fmaf(__uint_as_float(w << 16),          hx, a0);
    a1 = fmaf(__uint_as_float(w & 0xFFFF0000u),  hy, a1);
}

__global__ void init_pub() {
    int i = blockIdx.x * blockDim.x + threadIdx.x;
    if (i < 2 * 2 * HID) ((unsigned*)g_pubP)[i] = 0u;
}

// ---- input GEMM: out[512][4096] = A[512,K](lda) * W[4096,K]^T + b1+b2 (fp32 exact) ----
#define GBM 64
#define GBN 64
#define GBK 16
__global__ __launch_bounds__(256)
void gemm_gx(const float* __restrict__ A, int lda,
             const float* __restrict__ Wt,
             const float* __restrict__ b1, const float* __restrict__ b2,
             float* __restrict__ out, int K)
{
    __shared__ float As[GBK][GBM + 4];
    __shared__ float Bs[GBK][GBN + 4];
    const int bm = blockIdx.y * GBM, bn = blockIdx.x * GBN;
    const int tid = threadIdx.x;
    const int tx = tid & 15, ty = tid >> 4;
    const int lr = tid >> 2, lk = (tid & 3) * 4;

    float acc[4][4];
#pragma unroll
    for (int i = 0; i < 4; i++)
#pragma unroll
        for (int j = 0; j < 4; j++) acc[i][j] = 0.0f;

    for (int k0 = 0; k0 < K; k0 += GBK) {
        float4 a = *(const float4*)(A  + (size_t)(bm + lr) * lda + k0 + lk);
        float4 w = *(const float4*)(Wt + (size_t)(bn + lr) * K   + k0 + lk);
        As[lk+0][lr]=a.x; As[lk+1][lr]=a.y; As[lk+2][lr]=a.z; As[lk+3][lr]=a.w;
        Bs[lk+0][lr]=w.x; Bs[lk+1][lr]=w.y; Bs[lk+2][lr]=w.z; Bs[lk+3][lr]=w.w;
        __syncthreads();
#pragma unroll
        for (int k = 0; k < GBK; k++) {
            float4 av = *(const float4*)&As[k][ty*4];
            float4 bv = *(const float4*)&Bs[k][tx*4];
            acc[0][0]+=av.x*bv.x; acc[0][1]+=av.x*bv.y; acc[0][2]+=av.x*bv.z; acc[0][3]+=av.x*bv.w;
            acc[1][0]+=av.y*bv.x; acc[1][1]+=av.y*bv.y; acc[1][2]+=av.y*bv.z; acc[1][3]+=av.y*bv.w;
            acc[2][0]+=av.z*bv.x; acc[2][1]+=av.z*bv.y; acc[2][2]+=av.z*bv.z; acc[2][3]+=av.z*bv.w;
            acc[3][0]+=av.w*bv.x; acc[3][1]+=av.w*bv.y; acc[3][2]+=av.w*bv.z; acc[3][3]+=av.w*bv.w;
        }
        __syncthreads();
    }
    float4 bb1 = *(const float4*)(b1 + bn + tx*4);
    float4 bb2 = *(const float4*)(b2 + bn + tx*4);
    float bias[4] = { bb1.x+bb2.x, bb1.y+bb2.y, bb1.z+bb2.z, bb1.w+bb2.w };
#pragma unroll
    for (int i = 0; i < 4; i++) {
        size_t row = (size_t)(bm + ty*4 + i) * GATES + bn + tx*4;
#pragma unroll
        for (int j = 0; j < 4; j++) out[row + j] = acc[i][j] + bias[j];
    }
}

// ---------------- fused 2-layer scan: 513 rounds carry layers (a,b) ----------------
// Round t: compute h_a[t] (t<512) and h_b[t-1] (t>=1). Poll round t needs the
// round-(t-1) publishes: h_a[t-1] (tag t) and h_b[t-2] (tag t; t==1 uses the
// dummy-zero h_b[-1] published at round 0). Publish tag = (t+1)&0xFF.
// Weights bf16-packed in registers: per lane 3 matrices x 64 u32 regs.
__global__ __launch_bounds__(NTHR, 1)
void lstm_scan2(const float* __restrict__ whh_a,   // [4096,1024] layer a
                const float* __restrict__ whh_b,   // [4096,1024] layer b
                const float* __restrict__ wih_b,   // [4096,1024] layer b input
                const float* __restrict__ gx_a,    // [512,4096] layer-a input (+bias)
                const float* __restrict__ bih_b,
                const float* __restrict__ bhh_b,
                float* __restrict__ hist_b,        // [512,1024] layer-b h history
                unsigned* __restrict__ pub)        // [2048]
{
    __shared__ float sa[2][HID];   // staged h_a[t-1]
    __shared__ float sb[2][HID];   // staged h_b[t-2]

    const int cta  = blockIdx.x;
    const int tid  = threadIdx.x;
    const int warp = tid >> 5;
    const int lane = tid & 31;
    const int gate = lane >> 3;      // i,f,g,o
    const int kk   = lane & 7;       // 128-elem k-chunk
    const int unit = cta * 8 + warp; // 0..1023
    const size_t roff = (size_t)(gate * HID + unit) * HID + kk * 128;

    // load + convert weights to bf16 pairs (64 u32 regs per matrix)
    unsigned WA[64], WB[64], WI[64];
    {
        const float2* pa = (const float2*)(whh_a + roff);
        const float2* pb = (const float2*)(whh_b + roff);
        const float2* pi = (const float2*)(wih_b + roff);
#pragma unroll
        for (int j = 0; j < 64; j++) {
            float2 f = __ldg(pa + j);
            __nv_bfloat162 r = __floats2bfloat162_rn(f.x, f.y);
            WA[j] = *(unsigned*)&r;
        }
#pragma unroll
        for (int j = 0; j < 64; j++) {
            float2 f = __ldg(pb + j);
            __nv_bfloat162 r = __floats2bfloat162_rn(f.x, f.y);
            WB[j] = *(unsigned*)&r;
        }
#pragma unroll
        for (int j = 0; j < 64; j++) {
            float2 f = __ldg(pi + j);
            __nv_bfloat162 r = __floats2bfloat162_rn(f.x, f.y);
            WI[j] = *(unsigned*)&r;
        }
    }

    // layer-b bias on kk==1 lanes
    float bb = 0.0f;
    if (kk == 1) {
        int row = gate * HID + unit;
        bb = __ldg(&bih_b[row]) + __ldg(&bhh_b[row]);
    }

    float c_a = 0.0f, c_b = 0.0f;   // cell states (lane 0)

    for (int t = 0; t <= SEQ; t++) {
        const int buf = t & 1;

        float gxa = 0.0f;
        if (kk == 0 && t < SEQ)
            gxa = __ldg(&gx_a[(size_t)t * GATES + gate * HID + unit]);

        float acc_a = 0.0f, acc_b = 0.0f;
        if (t >= 1) {
            // poll both halves (2048 words) with 2 vector loads per thread
            const unsigned expt = (unsigned)t & 0xFFu;
            const uint4* pv = (const uint4*)pub;
            uint4 A, B;
            for (;;) {
                A = ld_rlx4(pv + tid);          // h_a words 4tid..4tid+3
                B = ld_rlx4(pv + tid + 256);    // h_b words
                unsigned bad = ((A.x^expt)|(A.y^expt)|(A.z^expt)|(A.w^expt)|
                                (B.x^expt)|(B.y^expt)|(B.z^expt)|(B.w^expt)) & 0xFFu;
                if (bad == 0u) break;
            }
            ((float4*)sa[buf])[tid] = make_float4(
                __uint_as_float(A.x & 0xFFFFFF00u), __uint_as_float(A.y & 0xFFFFFF00u),
                __uint_as_float(A.z & 0xFFFFFF00u), __uint_as_float(A.w & 0xFFFFFF00u));
            ((float4*)sb[buf])[tid] = make_float4(
                __uint_as_float(B.x & 0xFFFFFF00u), __uint_as_float(B.y & 0xFFFFFF00u),
                __uint_as_float(B.z & 0xFFFFFF00u), __uint_as_float(B.w & 0xFFFFFF00u));
            __syncthreads();

            // 3 GEMVs: a = WA.ha ; b = WB.hb + WI.ha
            const float4* ha = (const float4*)&sa[buf][kk * 128];
            const float4* hb = (const float4*)&sb[buf][kk * 128];
            float a0 = 0.f, a1 = 0.f, b0 = 0.f, b1 = 0.f;
#pragma unroll
            for (int i = 0; i < 32; i++) {
                float4 va = ha[i];
                bfma(WA[2*i],   va.x, va.y, a0, a1);
                bfma(WA[2*i+1], va.z, va.w, a0, a1);
                bfma(WI[2*i],   va.x, va.y, b0, b1);
                bfma(WI[2*i+1], va.z, va.w, b0, b1);
                float4 vb = hb[i];
                bfma(WB[2*i],   vb.x, vb.y, b0, b1);
                bfma(WB[2*i+1], vb.z, vb.w, b0, b1);
            }
            acc_a = a0 + a1;
            acc_b = b0 + b1;
        }

        // reduce each gate's 8 lanes (leaders at lanes 0,8,16,24)
        acc_a += __shfl_down_sync(0xffffffffu, acc_a, 4);
        acc_a += __shfl_down_sync(0xffffffffu, acc_a, 2);
        acc_a += __shfl_down_sync(0xffffffffu, acc_a, 1);
        acc_b += __shfl_down_sync(0xffffffffu, acc_b, 4);
        acc_b += __shfl_down_sync(0xffffffffu, acc_b, 2);
        acc_b += __shfl_down_sync(0xffffffffu, acc_b, 1);
        // broadcast b's group sum so kk==1 lanes can do its activation
        float accb_all = __shfl_sync(0xffffffffu, acc_b, lane & 24);

        float act = 0.0f;
        if (kk == 0) { float g = acc_a + gxa; act = (gate == 2) ? tanh_fast(g) : sigm_fast(g); }
        if (kk == 1) { float g = accb_all + bb; act = (gate == 2) ? tanh_fast(g) : sigm_fast(g); }

        float ai_a = __shfl_sync(0xffffffffu, act, 0);
        float af_a = __shfl_sync(0xffffffffu, act, 8);
        float ag_a = __shfl_sync(0xffffffffu, act, 16);
        float ao_a = __shfl_sync(0xffffffffu, act, 24);
        float ai_b = __shfl_sync(0xffffffffu, act, 1);
        float af_b = __shfl_sync(0xffffffffu, act, 9);
        float ag_b = __shfl_sync(0xffffffffu, act, 17);
        float ao_b = __shfl_sync(0xffffffffu, act, 25);

        if (lane == 0) {
            const unsigned tag = (unsigned)(t + 1) & 0xFFu;
            if (t < SEQ) {   // h_a[t]
                c_a = af_a * c_a + ai_a * ag_a;
                float h = ao_a * tanh_fast(c_a);
                st_rlx(pub + unit, (__float_as_uint(h) & 0xFFFFFF00u) | tag);
            }
            if (t >= 1) {    // h_b[t-1]
                c_b = af_b * c_b + ai_b * ag_b;
                float h = ao_b * tanh_fast(c_b);
                unsigned hb_ = __float_as_uint(h) & 0xFFFFFF00u;
                if (t < SEQ) st_rlx(pub + HID + unit, hb_ | tag);
                hist_b[(size_t)(t - 1) * HID + unit] = __uint_as_float(hb_);
            } else {         // round 0: dummy-zero h_b[-1]
                st_rlx(pub + HID + unit, 0u | tag);
            }
        }
        // one barrier per round (inside t>=1 branch); smem double-buffered
    }
}

// ---------------- final FC ----------------
__global__ void final_fc(const float* __restrict__ h,
                         const float* __restrict__ fcw,
                         const float* __restrict__ fcb,
                         float* __restrict__ out)
{
    const int t = blockIdx.x;
    const int tid = threadIdx.x;
    float s = 0.0f;
    for (int j = tid; j < HID; j += 128)
        s += fcw[j] * sigm_fast(h[(size_t)t * HID + j]);
    s += __shfl_down_sync(0xffffffffu, s, 16);
    s += __shfl_down_sync(0xffffffffu, s, 8);
    s += __shfl_down_sync(0xffffffffu, s, 4);
    s += __shfl_down_sync(0xffffffffu, s, 2);
    s += __shfl_down_sync(0xffffffffu, s, 1);
    __shared__ float red[4];
    if ((tid & 31) == 0) red[tid >> 5] = s;
    __syncthreads();
    if (tid == 0) out[t] = red[0] + red[1] + red[2] + red[3] + fcb[0];
}

// ---------------- launch ----------------
extern "C" void kernel_launch(void* const* d_in, const int* in_sizes, int n_in,
                              void* d_out, int out_size)
{
    const float* x         = (const float*)d_in[0];  // [512,64,512]
    const float* w_ih0     = (const float*)d_in[1];  // [4096,512]
    const float* w_ih_rest = (const float*)d_in[2];  // [3,4096,1024]
    const float* w_hh      = (const float*)d_in[3];  // [4,4096,1024]
    const float* b_ih      = (const float*)d_in[4];  // [4,4096]
    const float* b_hh      = (const float*)d_in[5];  // [4,4096]
    const float* fc_w      = (const float*)d_in[6];  // [1,1024]
    const float* fc_b      = (const float*)d_in[7];  // [1]
    float* out             = (float*)d_out;          // [512,1]

    float *gx, *h1, *h3; unsigned* pubP;
    cudaGetSymbolAddress((void**)&gx,   g_gx);
    cudaGetSymbolAddress((void**)&h1,   g_h1);
    cudaGetSymbolAddress((void**)&h3,   g_h3);
    cudaGetSymbolAddress((void**)&pubP, g_pubP);

    dim3 ggrid(GATES / GBN, SEQ / GBM);

    init_pub<<<(4 * HID + 255) / 256, 256>>>();

    // pair (0,1): gx0 from x row 63 (fp32 exact), fused scan -> h1 history
    gemm_gx<<<ggrid, 256>>>(x + (size_t)63 * INDIM, 64 * INDIM,
                            w_ih0, b_ih, b_hh, gx, INDIM);
    lstm_scan2<<<NCTA, NTHR>>>(w_hh,                         // layer 0 hh
                               w_hh + (size_t)1 * GATES * HID, // layer 1 hh
                               w_ih_rest,                      // layer 1 ih
                               gx, b_ih + GATES, b_hh + GATES,
                               h1, pubP);

    // pair (2,3): gx2 from h1 (fp32 exact), fused scan -> h3 history
    gemm_gx<<<ggrid, 256>>>(h1, HID, w_ih_rest + (size_t)1 * GATES * HID,
                            b_ih + 2 * GATES, b_hh + 2 * GATES, gx, HID);
    lstm_scan2<<<NCTA, NTHR>>>(w_hh + (size_t)2 * GATES * HID,
                               w_hh + (size_t)3 * GATES * HID,
                               w_ih_rest + (size_t)2 * GATES * HID,
                               gx, b_ih + 3 * GATES, b_hh + 3 * GATES,
                               h3, pubP + 2 * HID);

    final_fc<<<SEQ, 128>>>(h3, fc_w, fc_b, out);
}

// round 17
// speedup vs baseline: 1.6273x; 1.6273x over previous
#include <cuda_runtime.h>
#include <math.h>

// Problem constants
#define SEQ     512
#define INDIM   512
#define HID     1024
#define GATES   4096   // 4*HID, PyTorch gate order i,f,g,o
#define LAYERS  4

// Scan kernel config (R7 measured-best shape)
#define NCTA    128
#define NTHR    256
#define UPC     8      // h-units per CTA (one per warp)

// ---------------- device scratch (no allocations allowed) ----------------
__device__ float    g_gx[SEQ * GATES];        // 8 MB, per-layer input-GEMM result
__device__ float    g_h0[SEQ * HID];          // 2 MB ping (full h history)
__device__ float    g_h1[SEQ * HID];          // 2 MB pong
__device__ unsigned g_pub[LAYERS][HID];       // self-validating h words (24b h | 8b tag)

__device__ __forceinline__ float sigm_fast(float x) {
    return 1.0f / (1.0f + __expf(-x));
}
__device__ __forceinline__ float tanh_fast(float x) {
    return 1.0f - 2.0f / (1.0f + __expf(2.0f * x));
}
__device__ __forceinline__ void st_rlx(unsigned* p, unsigned v) {
    asm volatile("st.relaxed.gpu.global.u32 [%0], %1;" :: "l"(p), "r"(v) : "memory");
}
__device__ __forceinline__ uint4 ld_rlx4(const uint4* p) {
    uint4 v;
    asm volatile("ld.relaxed.gpu.global.v4.u32 {%0,%1,%2,%3}, [%4];"
                 : "=r"(v.x), "=r"(v.y), "=r"(v.z), "=r"(v.w) : "l"(p));
    return v;
}

// no-op spacer (keeps launch ordering stable across rounds)
__global__ void noop_k() {}

// ---- input GEMM: out[M=512][N=4096] = A[M][K](row stride lda) * W[N][K]^T + b1+b2 ----
#define GBM 64
#define GBN 64
#define GBK 16
__global__ __launch_bounds__(256)
void gemm_gx(const float* __restrict__ A,   // [512, K] rows strided by lda
             int lda,
             const float* __restrict__ Wt,  // [4096, K] row-major
             const float* __restrict__ b1,  // [4096]
             const float* __restrict__ b2,  // [4096]
             float* __restrict__ out,       // [512, 4096]
             int K)
{
    __shared__ float As[GBK][GBM + 4];
    __shared__ float Bs[GBK][GBN + 4];

    const int bm = blockIdx.y * GBM;
    const int bn = blockIdx.x * GBN;
    const int tid = threadIdx.x;
    const int tx = tid & 15;
    const int ty = tid >> 4;
    const int lr = tid >> 2;          // 0..63
    const int lk = (tid & 3) * 4;     // 0,4,8,12

    float acc[4][4];
#pragma unroll
    for (int i = 0; i < 4; i++)
#pragma unroll
        for (int j = 0; j < 4; j++) acc[i][j] = 0.0f;

    for (int k0 = 0; k0 < K; k0 += GBK) {
        float4 a = *(const float4*)(A  + (size_t)(bm + lr) * lda + k0 + lk);
        float4 w = *(const float4*)(Wt + (size_t)(bn + lr) * K   + k0 + lk);
        As[lk + 0][lr] = a.x; As[lk + 1][lr] = a.y; As[lk + 2][lr] = a.z; As[lk + 3][lr] = a.w;
        Bs[lk + 0][lr] = w.x; Bs[lk + 1][lr] = w.y; Bs[lk + 2][lr] = w.z; Bs[lk + 3][lr] = w.w;
        __syncthreads();
#pragma unroll
        for (int k = 0; k < GBK; k++) {
            float4 av = *(const float4*)&As[k][ty * 4];
            float4 bv = *(const float4*)&Bs[k][tx * 4];
            acc[0][0] += av.x * bv.x; acc[0][1] += av.x * bv.y; acc[0][2] += av.x * bv.z; acc[0][3] += av.x * bv.w;
            acc[1][0] += av.y * bv.x; acc[1][1] += av.y * bv.y; acc[1][2] += av.y * bv.z; acc[1][3] += av.y * bv.w;
            acc[2][0] += av.z * bv.x; acc[2][1] += av.z * bv.y; acc[2][2] += av.z * bv.z; acc[2][3] += av.z * bv.w;
            acc[3][0] += av.w * bv.x; acc[3][1] += av.w * bv.y; acc[3][2] += av.w * bv.z; acc[3][3] += av.w * bv.w;
        }
        __syncthreads();
    }

    float4 bb1 = *(const float4*)(b1 + bn + tx * 4);
    float4 bb2 = *(const float4*)(b2 + bn + tx * 4);
    float bias[4] = { bb1.x + bb2.x, bb1.y + bb2.y, bb1.z + bb2.z, bb1.w + bb2.w };
#pragma unroll
    for (int i = 0; i < 4; i++) {
        size_t row = (size_t)(bm + ty * 4 + i) * GATES + bn + tx * 4;
#pragma unroll
        for (int j = 0; j < 4; j++)
            out[row + j] = acc[i][j] + bias[j];
    }
}

// ---------------- recurrent scan: 512 sequential steps, persistent grid ----------------
// R7 protocol (measured best), micro-optimized:
//   publish: one self-validating 32-bit word per h unit
//     bits[31:8] = fp32 h (mantissa truncated to 15 bits); bits[7:0] = (t+1)&0xFF
//   poll: ONE ld.relaxed.v4.u32 per thread (256 threads x 4 words = all 1024),
//     re-issued whole on any stale tag (parallel round trips, single issue slot)
//   stage: one STS.128 per thread into double-buffered smem
__global__ __launch_bounds__(NTHR, 1)
void lstm_scan(const float* __restrict__ w_hh_l,   // [4096,1024] this layer
               const float* __restrict__ gx,       // [512,4096] input-gemm+bias
               float* __restrict__ h_out,          // [512,1024] full history
               unsigned* __restrict__ pub)         // [HID] tagged h words
{
    __shared__ float sh[2][HID];   // 8KB double-buffered staged h_{t-1}

    const int cta  = blockIdx.x;
    const int tid  = threadIdx.x;
    const int warp = tid >> 5;            // 0..7 -> unit within CTA
    const int lane = tid & 31;
    const int gate = lane >> 3;           // 0..3 (i,f,g,o)
    const int kk   = lane & 7;            // k-chunk 0..7 (128 elems each)
    const int unit = cta * UPC + warp;    // 0..1023
    const int wrow = gate * HID + unit;   // row in W_hh

    // Load 128 weights (this lane's k-chunk of its gate row) into registers.
    float4 W[32];
    {
        const float4* wp = (const float4*)(w_hh_l + (size_t)wrow * HID + kk * 128);
#pragma unroll
        for (int i = 0; i < 32; i++) W[i] = __ldg(wp + i);
    }

    float c = 0.0f;   // cell state (valid on lane 0 of each warp)

    for (int t = 0; t < SEQ; t++) {
        // prefetch gx for this gate row (independent of the recurrence)
        float gxv = 0.0f;
        if (kk == 0) gxv = __ldg(&gx[(size_t)t * GATES + wrow]);

        float acc = 0.0f;
        if (t > 0) {
            // poll+fetch h_{t-1}: one vector load covers this thread's 4 words
            const unsigned expt = (unsigned)t & 0xFFu;
            const uint4* pv = (const uint4*)pub;
            uint4 A;
            for (;;) {
                A = ld_rlx4(pv + tid);   // words 4*tid .. 4*tid+3
                unsigned bad = ((A.x ^ expt) | (A.y ^ expt) |
                                (A.z ^ expt) | (A.w ^ expt)) & 0xFFu;
                if (bad == 0u) break;
            }
            ((float4*)sh[t & 1])[tid] = make_float4(
                __uint_as_float(A.x & 0xFFFFFF00u), __uint_as_float(A.y & 0xFFFFFF00u),
                __uint_as_float(A.z & 0xFFFFFF00u), __uint_as_float(A.w & 0xFFFFFF00u));
            __syncthreads();

            // GEMV: 4 independent fmaf chains (32-deep each)
            const float4* hs = (const float4*)&sh[t & 1][kk * 128];
            float a0 = 0.0f, a1 = 0.0f, a2 = 0.0f, a3 = 0.0f;
#pragma unroll
            for (int i = 0; i < 32; i++) {
                float4 hv = hs[i];
                a0 = fmaf(W[i].x, hv.x, a0);
                a1 = fmaf(W[i].y, hv.y, a1);
                a2 = fmaf(W[i].z, hv.z, a2);
                a3 = fmaf(W[i].w, hv.w, a3);
            }
            acc = (a0 + a1) + (a2 + a3);
        }

        // reduce the 8 lanes of each gate group
        acc += __shfl_down_sync(0xffffffffu, acc, 4);
        acc += __shfl_down_sync(0xffffffffu, acc, 2);
        acc += __shfl_down_sync(0xffffffffu, acc, 1);

        float gval = acc + gxv;   // meaningful on kk==0 lanes (0,8,16,24)

        // activations in parallel on the 4 group-leader lanes (g-gate -> tanh)
        float act = (gate == 2) ? tanh_fast(gval) : sigm_fast(gval);
        float ai = __shfl_sync(0xffffffffu, act, 0);
        float af = __shfl_sync(0xffffffffu, act, 8);
        float ag = __shfl_sync(0xffffffffu, act, 16);
        float ao = __shfl_sync(0xffffffffu, act, 24);

        if (lane == 0) {
            c = af * c + ai * ag;
            float h = ao * tanh_fast(c);
            unsigned hb = __float_as_uint(h) & 0xFFFFFF00u;
            st_rlx(pub + unit, hb | ((unsigned)(t + 1) & 0xFFu));  // publish: data IS flag
            h_out[(size_t)t * HID + unit] = __uint_as_float(hb);   // history (consistent)
        }
        // no end-of-step barrier: sh is double-buffered, pub is self-validating
    }
}

// ---------------- final FC: out[t] = sum_j sigmoid(h[t][j]) * fcw[j] + fcb ----------------
__global__ void final_fc(const float* __restrict__ h,
                         const float* __restrict__ fcw,
                         const float* __restrict__ fcb,
                         float* __restrict__ out)
{
    const int t = blockIdx.x;
    const int tid = threadIdx.x;   // 128 threads
    float s = 0.0f;
    for (int j = tid; j < HID; j += 128)
        s += fcw[j] * sigm_fast(h[(size_t)t * HID + j]);
    s += __shfl_down_sync(0xffffffffu, s, 16);
    s += __shfl_down_sync(0xffffffffu, s, 8);
    s += __shfl_down_sync(0xffffffffu, s, 4);
    s += __shfl_down_sync(0xffffffffu, s, 2);
    s += __shfl_down_sync(0xffffffffu, s, 1);
    __shared__ float red[4];
    if ((tid & 31) == 0) red[tid >> 5] = s;
    __syncthreads();
    if (tid == 0) out[t] = red[0] + red[1] + red[2] + red[3] + fcb[0];
}

// ---------------- launch ----------------
extern "C" void kernel_launch(void* const* d_in, const int* in_sizes, int n_in,
                              void* d_out, int out_size)
{
    const float* x         = (const float*)d_in[0];  // [512,64,512]
    const float* w_ih0     = (const float*)d_in[1];  // [4096,512]
    const float* w_ih_rest = (const float*)d_in[2];  // [3,4096,1024]
    const float* w_hh      = (const float*)d_in[3];  // [4,4096,1024]
    const float* b_ih      = (const float*)d_in[4];  // [4,4096]
    const float* b_hh      = (const float*)d_in[5];  // [4,4096]
    const float* fc_w      = (const float*)d_in[6];  // [1,1024]
    const float* fc_b      = (const float*)d_in[7];  // [1]
    float* out             = (float*)d_out;          // [512,1]

    float *gx, *h0, *h1; unsigned* pub;
    cudaGetSymbolAddress((void**)&gx,  g_gx);
    cudaGetSymbolAddress((void**)&h0,  g_h0);
    cudaGetSymbolAddress((void**)&h1,  g_h1);
    cudaGetSymbolAddress((void**)&pub, g_pub);

    dim3 ggrid(GATES / GBN, SEQ / GBM);   // (64, 8)

    gemm_gx<<<ggrid, 256>>>(x + (size_t)63 * INDIM, 64 * INDIM,
                            w_ih0, b_ih, b_hh, gx, INDIM);
    noop_k<<<1, 32>>>();
    noop_k<<<1, 32>>>();

    // layer 0 scan -> h1
    lstm_scan<<<NCTA, NTHR>>>(w_hh, gx, h1, pub + 0 * HID);

    // layer 1: h1 -> h0
    gemm_gx<<<ggrid, 256>>>(h1, HID, w_ih_rest,
                            b_ih + GATES, b_hh + GATES, gx, HID);
    lstm_scan<<<NCTA, NTHR>>>(w_hh + (size_t)1 * GATES * HID, gx, h0, pub + 1 * HID);

    // layer 2: h0 -> h1
    gemm_gx<<<ggrid, 256>>>(h0, HID, w_ih_rest + (size_t)1 * GATES * HID,
                            b_ih + 2 * GATES, b_hh + 2 * GATES, gx, HID);
    lstm_scan<<<NCTA, NTHR>>>(w_hh + (size_t)2 * GATES * HID, gx, h1, pub + 2 * HID);

    // layer 3: h1 -> h0
    gemm_gx<<<ggrid, 256>>>(h1, HID, w_ih_rest + (size_t)2 * GATES * HID,
                            b_ih + 3 * GATES, b_hh + 3 * GATES, gx, HID);
    lstm_scan<<<NCTA, NTHR>>>(w_hh + (size_t)3 * GATES * HID, gx, h0, pub + 3 * HID);

    final_fc<<<SEQ, 128>>>(h0, fc_w, fc_b, out);
}